// round 2
// baseline (speedup 1.0000x reference)
#include <cuda_runtime.h>
#include <math.h>
#include <stdint.h>

#define N_NODES 4096
#define BATCH   32
#define TSTEPS  16
#define DIM     8
#define HALFD   4
#define NCOMM   32
#define HID     64

// Scratch (no allocs allowed): causal graphs per community + class per node.
__device__ float g_graphs[NCOMM * DIM * DIM];
__device__ int   g_class[N_NODES];

// ---------------------------------------------------------------------------
// Kernel 1: community_class = argmax over C (first-max semantics, jnp.argmax)
// ---------------------------------------------------------------------------
__global__ void classify_kernel(const float* __restrict__ community) {
    int n = blockIdx.x * blockDim.x + threadIdx.x;
    if (n >= N_NODES) return;
    const float* row = community + (size_t)n * NCOMM;
    float best = row[0];
    int bi = 0;
    #pragma unroll
    for (int c = 1; c < NCOMM; c++) {
        float v = row[c];
        if (v > best) { best = v; bi = c; }
    }
    g_class[n] = bi;
}

// ---------------------------------------------------------------------------
// Kernel 2: eigen-based causal graphs for the 32 koopman matrices.
// G = sum_i (lam_i + (1e-10+1e-10i)) * mask_i * P_i,
// P_i = prod_{j!=i} (A - lam_j I) / (lam_i - lam_j)   (Lagrange projector).
// Eigenvalues via char-poly (Faddeev-LeVerrier, double) + Durand-Kerner + Newton.
// One block of 256 threads: thread t -> (matrix c = t>>3, root i = t&7).
// ---------------------------------------------------------------------------
__global__ void eig_kernel(const float* __restrict__ koop) {
    __shared__ double sA[NCOMM][64];     // 16 KB
    __shared__ double sCoef[NCOMM][9];   // 2.25 KB
    __shared__ double sZr[NCOMM][8];
    __shared__ double sZi[NCOMM][8];
    __shared__ double sLMr[NCOMM][8];
    __shared__ double sLMi[NCOMM][8];
    __shared__ int    sAny[NCOMM];
    __shared__ double sG[NCOMM][64];     // 16 KB

    int t = threadIdx.x;

    for (int i = t; i < NCOMM * 64; i += 256) {
        sA[i >> 6][i & 63] = (double)koop[i];
        sG[i >> 6][i & 63] = 0.0;
    }
    __syncthreads();

    int c  = t >> 3;
    int li = t & 7;

    // ---- Phase 1: characteristic polynomial (one thread per matrix) ----
    if (li == 0) {
        double M[64], Mn[64];
        #pragma unroll 1
        for (int i = 0; i < 64; i++) M[i] = sA[c][i];
        double tr = 0.0;
        for (int i = 0; i < 8; i++) tr += M[i * 9];
        sCoef[c][0] = 1.0;
        double ck = -tr;
        sCoef[c][1] = ck;
        #pragma unroll 1
        for (int k = 2; k <= 8; k++) {
            for (int i = 0; i < 8; i++) M[i * 9] += ck;
            #pragma unroll 1
            for (int r = 0; r < 8; r++) {
                for (int col = 0; col < 8; col++) {
                    double s = 0.0;
                    for (int q = 0; q < 8; q++) s += sA[c][r * 8 + q] * M[q * 8 + col];
                    Mn[r * 8 + col] = s;
                }
            }
            tr = 0.0;
            for (int i = 0; i < 8; i++) tr += Mn[i * 9];
            ck = -tr / (double)k;
            sCoef[c][k] = ck;
            #pragma unroll 1
            for (int i = 0; i < 64; i++) M[i] = Mn[i];
        }
    }
    __syncthreads();

    double co[9];
    #pragma unroll
    for (int k = 0; k <= 8; k++) co[k] = sCoef[c][k];

    // ---- Init roots: radius from |det|^{1/8}, asymmetric phases ----
    {
        double r0 = pow(fabs(co[8]) + 1e-30, 0.125);
        r0 = fmin(fmax(r0, 0.3), 3.0);
        double rr = r0 * (0.85 + 0.05 * (double)li);
        double th = 0.5 + 6.283185307179586 * (double)li / 8.0;
        sZr[c][li] = rr * cos(th);
        sZi[c][li] = rr * sin(th);
    }
    __syncthreads();

    // ---- Durand-Kerner (Jacobi), 100 iterations ----
    for (int it = 0; it < 100; it++) {
        double zr = sZr[c][li], zi = sZi[c][li];
        double pr = co[0], pi = 0.0;
        #pragma unroll
        for (int k = 1; k <= 8; k++) {
            double npr = pr * zr - pi * zi + co[k];
            double npi = pr * zi + pi * zr;
            pr = npr; pi = npi;
        }
        double dr = 1.0, di = 0.0;
        #pragma unroll
        for (int j = 0; j < 8; j++) {
            if (j == li) continue;
            double wr = zr - sZr[c][j], wi = zi - sZi[c][j];
            double nr = dr * wr - di * wi;
            double ni = dr * wi + di * wr;
            dr = nr; di = ni;
        }
        double dn = dr * dr + di * di + 1e-300;
        double qr = (pr * dr + pi * di) / dn;
        double qi = (pi * dr - pr * di) / dn;
        __syncthreads();
        sZr[c][li] = zr - qr;
        sZi[c][li] = zi - qi;
        __syncthreads();
    }

    // ---- Newton polish (3 steps, independent per root) ----
    {
        double zr = sZr[c][li], zi = sZi[c][li];
        for (int it = 0; it < 3; it++) {
            double pr = co[0], pi = 0.0, dr = 0.0, di = 0.0;
            #pragma unroll
            for (int k = 1; k <= 8; k++) {
                double ndr = dr * zr - di * zi + pr;
                double ndi = dr * zi + di * zr + pi;
                double npr = pr * zr - pi * zi + co[k];
                double npi = pr * zi + pi * zr;
                dr = ndr; di = ndi; pr = npr; pi = npi;
            }
            double dn = dr * dr + di * di + 1e-300;
            zr -= (pr * dr + pi * di) / dn;
            zi -= (pi * dr - pr * di) / dn;
        }
        __syncthreads();
        sZr[c][li] = zr;
        sZi[c][li] = zi;
    }
    __syncthreads();

    // ---- Mask: keep |lam + 1e-10(1+i)| in [0.9, 1.1], else keep all ----
    if (li == 0) sAny[c] = 0;
    __syncthreads();
    {
        double zsr = sZr[c][li] + 1e-10;
        double zsi = sZi[c][li] + 1e-10;
        double am = sqrt(zsr * zsr + zsi * zsi);
        int inband = (am <= 1.1 && am >= 0.9) ? 1 : 0;
        if (inband) atomicOr(&sAny[c], 1);
        __syncthreads();
        int keep = sAny[c] ? inband : 1;
        sLMr[c][li] = keep ? zsr : 0.0;
        sLMi[c][li] = keep ? zsi : 0.0;
    }
    __syncthreads();

    // ---- Projector contribution of this root (column-wise matvecs) ----
    {
        double lmr = sLMr[c][li], lmi = sLMi[c][li];
        if (lmr != 0.0 || lmi != 0.0) {
            double zir = sZr[c][li], zii = sZi[c][li];
            double dr = 1.0, di = 0.0;
            #pragma unroll
            for (int j = 0; j < 8; j++) {
                if (j == li) continue;
                double wr = zir - sZr[c][j], wi = zii - sZi[c][j];
                double nr = dr * wr - di * wi;
                double ni = dr * wi + di * wr;
                dr = nr; di = ni;
            }
            double dn = dr * dr + di * di + 1e-300;
            double cr = (lmr * dr + lmi * di) / dn;
            double ci = (lmi * dr - lmr * di) / dn;

            for (int col = 0; col < 8; col++) {
                double vr[8], vi[8];
                #pragma unroll
                for (int d = 0; d < 8; d++) { vr[d] = (d == col) ? 1.0 : 0.0; vi[d] = 0.0; }
                #pragma unroll
                for (int j = 0; j < 8; j++) {
                    if (j == li) continue;
                    double zjr = sZr[c][j], zji = sZi[c][j];
                    double nvr[8], nvi[8];
                    #pragma unroll
                    for (int r = 0; r < 8; r++) {
                        double sr = 0.0, si = 0.0;
                        #pragma unroll
                        for (int q = 0; q < 8; q++) {
                            double a = sA[c][r * 8 + q];
                            sr += a * vr[q];
                            si += a * vi[q];
                        }
                        nvr[r] = sr - (zjr * vr[r] - zji * vi[r]);
                        nvi[r] = si - (zjr * vi[r] + zji * vr[r]);
                    }
                    #pragma unroll
                    for (int r = 0; r < 8; r++) { vr[r] = nvr[r]; vi[r] = nvi[r]; }
                }
                #pragma unroll
                for (int d = 0; d < 8; d++) {
                    double val = cr * vr[d] - ci * vi[d];
                    atomicAdd(&sG[c][d * 8 + col], val);
                }
            }
        }
    }
    __syncthreads();

    for (int i = t; i < NCOMM * 64; i += 256)
        g_graphs[i] = (float)sG[i >> 6][i & 63];
}

// ---------------------------------------------------------------------------
// Kernel 3: fused parent-matvec + 3 coupling blocks + logprob.
// One point per thread; weights in dynamic shared (broadcast LDS).
// grid = (N_NODES, 2), block = 256; blockIdx.y*256+tid -> (b, t).
// ---------------------------------------------------------------------------
__global__ void __launch_bounds__(256, 1)
main_kernel(const float* __restrict__ latent,
            const float* __restrict__ W0, const float* __restrict__ b0,
            const float* __restrict__ W1, const float* __restrict__ b1,
            const float* __restrict__ W2, const float* __restrict__ b2,
            float* __restrict__ out)
{
    extern __shared__ float sm[];
    float* sW0 = sm;            // 3*12*64 = 2304
    float* sB0 = sW0 + 2304;    // 192
    float* sW1 = sB0 + 192;     // 12288
    float* sB1 = sW1 + 12288;   // 192
    float* sW2 = sB1 + 192;     // 1536
    float* sB2 = sW2 + 1536;    // 24
    float* sG  = sB2 + 24;      // 64  -> total 16600 floats = 66400 B

    int n   = blockIdx.x;
    int tid = threadIdx.x;

    for (int i = tid; i < 2304;  i += 256) sW0[i] = __ldg(W0 + i);
    for (int i = tid; i < 192;   i += 256) sB0[i] = __ldg(b0 + i);
    for (int i = tid; i < 12288; i += 256) sW1[i] = __ldg(W1 + i);
    for (int i = tid; i < 192;   i += 256) sB1[i] = __ldg(b1 + i);
    for (int i = tid; i < 1536;  i += 256) sW2[i] = __ldg(W2 + i);
    for (int i = tid; i < 24;    i += 256) sB2[i] = __ldg(b2 + i);
    if (tid < 64) {
        int cls = g_class[n];
        sG[tid] = g_graphs[cls * 64 + tid];
    }
    __syncthreads();

    int idx = blockIdx.y * 256 + tid;      // 0..511
    int b = idx >> 4;
    int t = idx & 15;
    size_t point = (((size_t)b * N_NODES + n) * TSTEPS + t);
    const float* xp = latent + point * DIM;

    float x[8];
    {
        float4 v0 = *(const float4*)(xp);
        float4 v1 = *(const float4*)(xp + 4);
        x[0] = v0.x; x[1] = v0.y; x[2] = v0.z; x[3] = v0.w;
        x[4] = v1.x; x[5] = v1.y; x[6] = v1.z; x[7] = v1.w;
    }

    // parent_e = sum_d x_d * G[d][e]   (computed from ORIGINAL latent)
    float cond[8];
    #pragma unroll
    for (int e = 0; e < 8; e++) {
        float s = 0.f;
        #pragma unroll
        for (int d = 0; d < 8; d++) s += x[d] * sG[d * 8 + e];
        cond[e] = s;
    }

    float logdet = 0.f;

    #pragma unroll
    for (int blk = 0; blk < 3; blk++) {
        const float* w0  = sW0 + blk * 768;
        const float* bb0 = sB0 + blk * 64;
        const float* w1  = sW1 + blk * 4096;
        const float* bb1 = sB1 + blk * 64;
        const float* w2  = sW2 + blk * 512;
        const float* bb2 = sB2 + blk * 8;
        const int po = (blk & 1) ? 4 : 0;   // passive half (input to MLP)
        const int ao = (blk & 1) ? 0 : 4;   // active half (transformed)

        float in12[12];
        #pragma unroll
        for (int m = 0; m < 4; m++) in12[m] = x[po + m];
        #pragma unroll
        for (int m = 0; m < 8; m++) in12[4 + m] = cond[m];

        // Layer 0: 12 -> 64, ReLU
        float h1[64];
        #pragma unroll
        for (int j = 0; j < 64; j++) h1[j] = bb0[j];
        #pragma unroll
        for (int k = 0; k < 12; k++) {
            float v = in12[k];
            const float4* wr = (const float4*)(w0 + (k << 6));
            #pragma unroll
            for (int j4 = 0; j4 < 16; j4++) {
                float4 w = wr[j4];
                h1[j4 * 4 + 0] += v * w.x;
                h1[j4 * 4 + 1] += v * w.y;
                h1[j4 * 4 + 2] += v * w.z;
                h1[j4 * 4 + 3] += v * w.w;
            }
        }
        #pragma unroll
        for (int j = 0; j < 64; j++) h1[j] = fmaxf(h1[j], 0.f);

        // Layer 1: 64 -> 64, ReLU
        float h2[64];
        #pragma unroll
        for (int j = 0; j < 64; j++) h2[j] = bb1[j];
        #pragma unroll
        for (int k = 0; k < 64; k++) {
            float v = h1[k];
            const float4* wr = (const float4*)(w1 + (k << 6));
            #pragma unroll
            for (int j4 = 0; j4 < 16; j4++) {
                float4 w = wr[j4];
                h2[j4 * 4 + 0] += v * w.x;
                h2[j4 * 4 + 1] += v * w.y;
                h2[j4 * 4 + 2] += v * w.z;
                h2[j4 * 4 + 3] += v * w.w;
            }
        }
        #pragma unroll
        for (int j = 0; j < 64; j++) h2[j] = fmaxf(h2[j], 0.f);

        // Layer 2: 64 -> 8
        float o[8];
        #pragma unroll
        for (int j = 0; j < 8; j++) o[j] = bb2[j];
        #pragma unroll
        for (int k = 0; k < 64; k++) {
            float v = h2[k];
            const float4* wr = (const float4*)(w2 + (k << 3));
            float4 wa = wr[0];
            float4 wb = wr[1];
            o[0] += v * wa.x; o[1] += v * wa.y; o[2] += v * wa.z; o[3] += v * wa.w;
            o[4] += v * wb.x; o[5] += v * wb.y; o[6] += v * wb.z; o[7] += v * wb.w;
        }

        #pragma unroll
        for (int m = 0; m < 4; m++) {
            float s = tanhf(o[m]);
            x[ao + m] = x[ao + m] * expf(s) + o[4 + m];
            logdet += s;
        }
    }

    float ss = 0.f;
    #pragma unroll
    for (int d = 0; d < 8; d++) ss += x[d] * x[d];

    out[point] = -0.5f * ss - 7.3515082656373812f + logdet;
}

// ---------------------------------------------------------------------------
extern "C" void kernel_launch(void* const* d_in, const int* in_sizes, int n_in,
                              void* d_out, int out_size)
{
    const float* latent    = (const float*)d_in[0];
    const float* koopman   = (const float*)d_in[1];
    const float* community = (const float*)d_in[2];
    const float* W0 = (const float*)d_in[3];
    const float* b0 = (const float*)d_in[4];
    const float* W1 = (const float*)d_in[5];
    const float* b1 = (const float*)d_in[6];
    const float* W2 = (const float*)d_in[7];
    const float* b2 = (const float*)d_in[8];
    float* out = (float*)d_out;

    static bool attr_set = false;
    if (!attr_set) {
        cudaFuncSetAttribute(main_kernel,
                             cudaFuncAttributeMaxDynamicSharedMemorySize, 66400);
        attr_set = true;
    }

    classify_kernel<<<N_NODES / 256, 256>>>(community);
    eig_kernel<<<1, 256>>>(koopman);
    main_kernel<<<dim3(N_NODES, 2), 256, 66400>>>(latent, W0, b0, W1, b1, W2, b2, out);
}

// round 4
// speedup vs baseline: 1.6607x; 1.6607x over previous
#include <cuda_runtime.h>
#include <math.h>
#include <stdint.h>

#define N_NODES 4096
#define BATCH   32
#define TSTEPS  16
#define DIM     8
#define HALFD   4
#define NCOMM   32
#define HID     64

// Scratch (no allocs allowed): causal graphs per community + class per node.
__device__ float g_graphs[NCOMM * DIM * DIM];
__device__ int   g_class[N_NODES];

// ---------------------------------------------------------------------------
// Kernel 1: community_class = argmax over C (first-max semantics, jnp.argmax)
// ---------------------------------------------------------------------------
__global__ void classify_kernel(const float* __restrict__ community) {
    int n = blockIdx.x * blockDim.x + threadIdx.x;
    if (n >= N_NODES) return;
    const float* row = community + (size_t)n * NCOMM;
    float best = row[0];
    int bi = 0;
    #pragma unroll
    for (int c = 1; c < NCOMM; c++) {
        float v = row[c];
        if (v > best) { best = v; bi = c; }
    }
    g_class[n] = bi;
}

// ---------------------------------------------------------------------------
// Kernel 2: eigen-based causal graphs for the 32 koopman matrices.
// G = sum_i (lam_i + (1e-10+1e-10i)) * mask_i * P_i,
// P_i = prod_{j!=i} (A - lam_j I) / (lam_i - lam_j)   (Lagrange projector).
// Eigenvalues via char-poly (Faddeev-LeVerrier, double) + Durand-Kerner + Newton.
// One block of 256 threads: thread t -> (matrix c = t>>3, root i = t&7).
// ---------------------------------------------------------------------------
__global__ void eig_kernel(const float* __restrict__ koop) {
    __shared__ double sA[NCOMM][64];     // 16 KB
    __shared__ double sCoef[NCOMM][9];   // 2.25 KB
    __shared__ double sZr[NCOMM][8];
    __shared__ double sZi[NCOMM][8];
    __shared__ double sLMr[NCOMM][8];
    __shared__ double sLMi[NCOMM][8];
    __shared__ int    sAny[NCOMM];
    __shared__ double sG[NCOMM][64];     // 16 KB

    int t = threadIdx.x;

    for (int i = t; i < NCOMM * 64; i += 256) {
        sA[i >> 6][i & 63] = (double)koop[i];
        sG[i >> 6][i & 63] = 0.0;
    }
    __syncthreads();

    int c  = t >> 3;
    int li = t & 7;

    // ---- Phase 1: characteristic polynomial (one thread per matrix) ----
    if (li == 0) {
        double M[64], Mn[64];
        #pragma unroll 1
        for (int i = 0; i < 64; i++) M[i] = sA[c][i];
        double tr = 0.0;
        for (int i = 0; i < 8; i++) tr += M[i * 9];
        sCoef[c][0] = 1.0;
        double ck = -tr;
        sCoef[c][1] = ck;
        #pragma unroll 1
        for (int k = 2; k <= 8; k++) {
            for (int i = 0; i < 8; i++) M[i * 9] += ck;
            #pragma unroll 1
            for (int r = 0; r < 8; r++) {
                for (int col = 0; col < 8; col++) {
                    double s = 0.0;
                    for (int q = 0; q < 8; q++) s += sA[c][r * 8 + q] * M[q * 8 + col];
                    Mn[r * 8 + col] = s;
                }
            }
            tr = 0.0;
            for (int i = 0; i < 8; i++) tr += Mn[i * 9];
            ck = -tr / (double)k;
            sCoef[c][k] = ck;
            #pragma unroll 1
            for (int i = 0; i < 64; i++) M[i] = Mn[i];
        }
    }
    __syncthreads();

    double co[9];
    #pragma unroll
    for (int k = 0; k <= 8; k++) co[k] = sCoef[c][k];

    // ---- Init roots: radius from |det|^{1/8}, asymmetric phases ----
    {
        double r0 = pow(fabs(co[8]) + 1e-30, 0.125);
        r0 = fmin(fmax(r0, 0.3), 3.0);
        double rr = r0 * (0.85 + 0.05 * (double)li);
        double th = 0.5 + 6.283185307179586 * (double)li / 8.0;
        sZr[c][li] = rr * cos(th);
        sZi[c][li] = rr * sin(th);
    }
    __syncthreads();

    // ---- Durand-Kerner (Jacobi), 64 iterations ----
    for (int it = 0; it < 64; it++) {
        double zr = sZr[c][li], zi = sZi[c][li];
        double pr = co[0], pi = 0.0;
        #pragma unroll
        for (int k = 1; k <= 8; k++) {
            double npr = pr * zr - pi * zi + co[k];
            double npi = pr * zi + pi * zr;
            pr = npr; pi = npi;
        }
        double dr = 1.0, di = 0.0;
        #pragma unroll
        for (int j = 0; j < 8; j++) {
            if (j == li) continue;
            double wr = zr - sZr[c][j], wi = zi - sZi[c][j];
            double nr = dr * wr - di * wi;
            double ni = dr * wi + di * wr;
            dr = nr; di = ni;
        }
        double dn = dr * dr + di * di + 1e-300;
        double qr = (pr * dr + pi * di) / dn;
        double qi = (pi * dr - pr * di) / dn;
        __syncthreads();
        sZr[c][li] = zr - qr;
        sZi[c][li] = zi - qi;
        __syncthreads();
    }

    // ---- Newton polish (3 steps, independent per root) ----
    {
        double zr = sZr[c][li], zi = sZi[c][li];
        for (int it = 0; it < 3; it++) {
            double pr = co[0], pi = 0.0, dr = 0.0, di = 0.0;
            #pragma unroll
            for (int k = 1; k <= 8; k++) {
                double ndr = dr * zr - di * zi + pr;
                double ndi = dr * zi + di * zr + pi;
                double npr = pr * zr - pi * zi + co[k];
                double npi = pr * zi + pi * zr;
                dr = ndr; di = ndi; pr = npr; pi = npi;
            }
            double dn = dr * dr + di * di + 1e-300;
            zr -= (pr * dr + pi * di) / dn;
            zi -= (pi * dr - pr * di) / dn;
        }
        __syncthreads();
        sZr[c][li] = zr;
        sZi[c][li] = zi;
    }
    __syncthreads();

    // ---- Mask: keep |lam + 1e-10(1+i)| in [0.9, 1.1], else keep all ----
    if (li == 0) sAny[c] = 0;
    __syncthreads();
    {
        double zsr = sZr[c][li] + 1e-10;
        double zsi = sZi[c][li] + 1e-10;
        double am = sqrt(zsr * zsr + zsi * zsi);
        int inband = (am <= 1.1 && am >= 0.9) ? 1 : 0;
        if (inband) atomicOr(&sAny[c], 1);
        __syncthreads();
        int keep = sAny[c] ? inband : 1;
        sLMr[c][li] = keep ? zsr : 0.0;
        sLMi[c][li] = keep ? zsi : 0.0;
    }
    __syncthreads();

    // ---- Projector contribution of this root (column-wise matvecs) ----
    {
        double lmr = sLMr[c][li], lmi = sLMi[c][li];
        if (lmr != 0.0 || lmi != 0.0) {
            double zir = sZr[c][li], zii = sZi[c][li];
            double dr = 1.0, di = 0.0;
            #pragma unroll
            for (int j = 0; j < 8; j++) {
                if (j == li) continue;
                double wr = zir - sZr[c][j], wi = zii - sZi[c][j];
                double nr = dr * wr - di * wi;
                double ni = dr * wi + di * wr;
                dr = nr; di = ni;
            }
            double dn = dr * dr + di * di + 1e-300;
            double cr = (lmr * dr + lmi * di) / dn;
            double ci = (lmi * dr - lmr * di) / dn;

            for (int col = 0; col < 8; col++) {
                double vr[8], vi[8];
                #pragma unroll
                for (int d = 0; d < 8; d++) { vr[d] = (d == col) ? 1.0 : 0.0; vi[d] = 0.0; }
                #pragma unroll
                for (int j = 0; j < 8; j++) {
                    if (j == li) continue;
                    double zjr = sZr[c][j], zji = sZi[c][j];
                    double nvr[8], nvi[8];
                    #pragma unroll
                    for (int r = 0; r < 8; r++) {
                        double sr = 0.0, si = 0.0;
                        #pragma unroll
                        for (int q = 0; q < 8; q++) {
                            double a = sA[c][r * 8 + q];
                            sr += a * vr[q];
                            si += a * vi[q];
                        }
                        nvr[r] = sr - (zjr * vr[r] - zji * vi[r]);
                        nvi[r] = si - (zjr * vi[r] + zji * vr[r]);
                    }
                    #pragma unroll
                    for (int r = 0; r < 8; r++) { vr[r] = nvr[r]; vi[r] = nvi[r]; }
                }
                #pragma unroll
                for (int d = 0; d < 8; d++) {
                    double val = cr * vr[d] - ci * vi[d];
                    atomicAdd(&sG[c][d * 8 + col], val);
                }
            }
        }
    }
    __syncthreads();

    for (int i = t; i < NCOMM * 64; i += 256)
        g_graphs[i] = (float)sG[i >> 6][i & 63];
}

// ---------------------------------------------------------------------------
// Kernel 3: fused parent-matvec + 3 coupling blocks + logprob.
// One point per thread; weights in dynamic shared (broadcast LDS).
// Layer1 and layer2 are FUSED in 16-wide chunks of the hidden dim so h2 is
// never fully materialized: live regs ~110-125 -> 2 CTAs/SM (16 warps).
// grid = (N_NODES, 2), block = 256; blockIdx.y*256+tid -> (b, t).
// ---------------------------------------------------------------------------
__global__ void __launch_bounds__(256, 2)
main_kernel(const float* __restrict__ latent,
            const float* __restrict__ W0, const float* __restrict__ b0,
            const float* __restrict__ W1, const float* __restrict__ b1,
            const float* __restrict__ W2, const float* __restrict__ b2,
            float* __restrict__ out)
{
    extern __shared__ float sm[];
    float* sW0 = sm;            // 3*12*64 = 2304
    float* sB0 = sW0 + 2304;    // 192
    float* sW1 = sB0 + 192;     // 12288
    float* sB1 = sW1 + 12288;   // 192
    float* sW2 = sB1 + 192;     // 1536
    float* sB2 = sW2 + 1536;    // 24
    float* sG  = sB2 + 24;      // 64  -> total 16600 floats = 66400 B

    int n   = blockIdx.x;
    int tid = threadIdx.x;

    for (int i = tid; i < 2304;  i += 256) sW0[i] = __ldg(W0 + i);
    for (int i = tid; i < 192;   i += 256) sB0[i] = __ldg(b0 + i);
    for (int i = tid; i < 12288; i += 256) sW1[i] = __ldg(W1 + i);
    for (int i = tid; i < 192;   i += 256) sB1[i] = __ldg(b1 + i);
    for (int i = tid; i < 1536;  i += 256) sW2[i] = __ldg(W2 + i);
    for (int i = tid; i < 24;    i += 256) sB2[i] = __ldg(b2 + i);
    if (tid < 64) {
        int cls = g_class[n];
        sG[tid] = g_graphs[cls * 64 + tid];
    }
    __syncthreads();

    int idx = blockIdx.y * 256 + tid;      // 0..511
    int b = idx >> 4;
    int t = idx & 15;
    size_t point = (((size_t)b * N_NODES + n) * TSTEPS + t);
    const float* xp = latent + point * DIM;

    float x[8];
    {
        float4 v0 = *(const float4*)(xp);
        float4 v1 = *(const float4*)(xp + 4);
        x[0] = v0.x; x[1] = v0.y; x[2] = v0.z; x[3] = v0.w;
        x[4] = v1.x; x[5] = v1.y; x[6] = v1.z; x[7] = v1.w;
    }

    // parent_e = sum_d x_d * G[d][e]   (computed from ORIGINAL latent)
    float cond[8];
    #pragma unroll
    for (int e = 0; e < 8; e++) {
        float s = 0.f;
        #pragma unroll
        for (int d = 0; d < 8; d++) s += x[d] * sG[d * 8 + e];
        cond[e] = s;
    }

    float logdet = 0.f;

    #pragma unroll
    for (int blk = 0; blk < 3; blk++) {
        const float* w0  = sW0 + blk * 768;
        const float* bb0 = sB0 + blk * 64;
        const float* w1  = sW1 + blk * 4096;
        const float* bb1 = sB1 + blk * 64;
        const float* w2  = sW2 + blk * 512;
        const float* bb2 = sB2 + blk * 8;
        const int po = (blk & 1) ? 4 : 0;   // passive half (input to MLP)
        const int ao = (blk & 1) ? 0 : 4;   // active half (transformed)

        float in12[12];
        #pragma unroll
        for (int m = 0; m < 4; m++) in12[m] = x[po + m];
        #pragma unroll
        for (int m = 0; m < 8; m++) in12[4 + m] = cond[m];

        // Layer 0: 12 -> 64, ReLU  (h1 fully register-resident)
        float h1[64];
        #pragma unroll
        for (int j = 0; j < 64; j++) h1[j] = bb0[j];
        #pragma unroll
        for (int k = 0; k < 12; k++) {
            float v = in12[k];
            const float4* wr = (const float4*)(w0 + (k << 6));
            #pragma unroll
            for (int j4 = 0; j4 < 16; j4++) {
                float4 w = wr[j4];
                h1[j4 * 4 + 0] += v * w.x;
                h1[j4 * 4 + 1] += v * w.y;
                h1[j4 * 4 + 2] += v * w.z;
                h1[j4 * 4 + 3] += v * w.w;
            }
        }
        #pragma unroll
        for (int j = 0; j < 64; j++) h1[j] = fmaxf(h1[j], 0.f);

        // Layers 1+2 fused: h2 computed in 16-wide chunks, immediately
        // reduced into o[8] and discarded (never 64 live h2 regs).
        float o[8];
        #pragma unroll
        for (int j = 0; j < 8; j++) o[j] = bb2[j];

        #pragma unroll
        for (int c4 = 0; c4 < 4; c4++) {
            float hc[16];
            #pragma unroll
            for (int j = 0; j < 16; j++) hc[j] = bb1[c4 * 16 + j];

            #pragma unroll
            for (int k = 0; k < 64; k++) {
                float v = h1[k];
                const float4* wr = (const float4*)(w1 + (k << 6) + (c4 << 4));
                #pragma unroll
                for (int j4 = 0; j4 < 4; j4++) {
                    float4 w = wr[j4];
                    hc[j4 * 4 + 0] += v * w.x;
                    hc[j4 * 4 + 1] += v * w.y;
                    hc[j4 * 4 + 2] += v * w.z;
                    hc[j4 * 4 + 3] += v * w.w;
                }
            }

            #pragma unroll
            for (int j = 0; j < 16; j++) {
                float v = fmaxf(hc[j], 0.f);
                const float4* wr = (const float4*)(w2 + ((c4 * 16 + j) << 3));
                float4 wa = wr[0];
                float4 wb = wr[1];
                o[0] += v * wa.x; o[1] += v * wa.y; o[2] += v * wa.z; o[3] += v * wa.w;
                o[4] += v * wb.x; o[5] += v * wb.y; o[6] += v * wb.z; o[7] += v * wb.w;
            }
        }

        #pragma unroll
        for (int m = 0; m < 4; m++) {
            float s = tanhf(o[m]);
            x[ao + m] = x[ao + m] * expf(s) + o[4 + m];
            logdet += s;
        }
    }

    float ss = 0.f;
    #pragma unroll
    for (int d = 0; d < 8; d++) ss += x[d] * x[d];

    out[point] = -0.5f * ss - 7.3515082656373812f + logdet;
}

// ---------------------------------------------------------------------------
extern "C" void kernel_launch(void* const* d_in, const int* in_sizes, int n_in,
                              void* d_out, int out_size)
{
    const float* latent    = (const float*)d_in[0];
    const float* koopman   = (const float*)d_in[1];
    const float* community = (const float*)d_in[2];
    const float* W0 = (const float*)d_in[3];
    const float* b0 = (const float*)d_in[4];
    const float* W1 = (const float*)d_in[5];
    const float* b1 = (const float*)d_in[6];
    const float* W2 = (const float*)d_in[7];
    const float* b2 = (const float*)d_in[8];
    float* out = (float*)d_out;

    cudaFuncSetAttribute(main_kernel,
                         cudaFuncAttributeMaxDynamicSharedMemorySize, 66400);

    classify_kernel<<<N_NODES / 256, 256>>>(community);
    eig_kernel<<<1, 256>>>(koopman);
    main_kernel<<<dim3(N_NODES, 2), 256, 66400>>>(latent, W0, b0, W1, b1, W2, b2, out);
}